// round 1
// baseline (speedup 1.0000x reference)
#include <cuda_runtime.h>
#include <math.h>

#define BATCH 8
#define TT 4096
#define NMELS 26
#define CONV_K 5
#define CH 64
#define WF 32
#define H1 256
#define H2 128
#define SHORT_W 8
#define SHORT_H 128

// scratch (device globals — no allocation allowed)
__device__ float g_xc[BATCH * TT * CH];   // conv output, relu'd
__device__ float g_a [BATCH * TT * CH];   // SE gate per (b,t,c)

// ---------------------------------------------------------------------------
// Kernel 1: causal conv1d (K=5, 26->64) + bias + relu
// grid: 8*64 blocks (64 tokens each), 256 threads
// ---------------------------------------------------------------------------
__global__ __launch_bounds__(256) void conv_kernel(
    const float* __restrict__ x, const float* __restrict__ cw,
    const float* __restrict__ cb)
{
    __shared__ float xsh[68 * NMELS];          // rows t0-4 .. t0+63
    __shared__ float wsh[CONV_K * NMELS * CH]; // 8320
    __shared__ float bsh[CH];

    const int b  = blockIdx.x >> 6;
    const int t0 = (blockIdx.x & 63) << 6;
    const int tid = threadIdx.x;

    for (int idx = tid; idx < 68 * NMELS; idx += 256) {
        int r = idx / NMELS, m = idx - r * NMELS;
        int t = t0 - 4 + r;
        xsh[idx] = (t >= 0) ? x[(b * TT + t) * NMELS + m] : 0.f;
    }
    for (int idx = tid; idx < CONV_K * NMELS * CH; idx += 256)
        wsh[idx] = cw[idx];
    if (tid < CH) bsh[tid] = cb[tid];
    __syncthreads();

    const int c  = tid & 63;
    const int tg = tid >> 6;   // 0..3, each handles 16 tokens

    float acc[16];
    #pragma unroll
    for (int i = 0; i < 16; ++i) acc[i] = bsh[c];

    #pragma unroll
    for (int k = 0; k < CONV_K; ++k) {
        #pragma unroll
        for (int m = 0; m < NMELS; ++m) {
            float w = wsh[(k * NMELS + m) * CH + c];
            int base = (tg * 16 + k) * NMELS + m;
            #pragma unroll
            for (int i = 0; i < 16; ++i)
                acc[i] = fmaf(xsh[base + i * NMELS], w, acc[i]);
        }
    }
    #pragma unroll
    for (int i = 0; i < 16; ++i) {
        int t = t0 + tg * 16 + i;
        g_xc[(b * TT + t) * CH + c] = fmaxf(acc[i], 0.f);
    }
}

// ---------------------------------------------------------------------------
// Kernel 2: SE gate. s = 32-frame causal mean of xc; a = sigmoid(relu(s@W1)@W2)
// grid: 8*32 blocks (128 tokens each), 256 threads, dynamic smem
// ---------------------------------------------------------------------------
__global__ __launch_bounds__(256) void se_kernel(
    const float* __restrict__ sew1, const float* __restrict__ seb1,
    const float* __restrict__ sew2, const float* __restrict__ seb2)
{
    extern __shared__ float sm2[];
    float* xsh = sm2;               // 159*64 = 10176
    float* ssh = sm2 + 10176;       // 128*65 = 8320 (padded stride 65)
    float* w1s = sm2 + 18496;       // 64*16
    float* w2s = sm2 + 19520;       // 16*64
    float* b1s = sm2 + 20544;       // 16
    float* b2s = sm2 + 20560;       // 64

    const int b  = blockIdx.x >> 5;
    const int t0 = (blockIdx.x & 31) << 7;
    const int tid = threadIdx.x;

    for (int idx = tid; idx < 159 * CH; idx += 256) {
        int r = idx >> 6, cc = idx & 63;
        int t = t0 - 31 + r;
        xsh[idx] = (t >= 0) ? g_xc[(b * TT + t) * CH + cc] : 0.f;
    }
    for (int idx = tid; idx < 1024; idx += 256) { w1s[idx] = sew1[idx]; w2s[idx] = sew2[idx]; }
    if (tid < 16) b1s[tid] = seb1[tid];
    if (tid < CH) b2s[tid] = seb2[tid];
    __syncthreads();

    // sliding 32-window sums: thread = (c, token-group of 32)
    {
        const int c  = tid & 63;
        const int tg = tid >> 6;
        const int tb = tg * 32;
        float ssum = 0.f;
        #pragma unroll
        for (int f = 0; f < WF; ++f) ssum += xsh[(tb + f) * CH + c];
        ssh[tb * 65 + c] = ssum * 0.03125f;
        for (int i = 1; i < 32; ++i) {
            ssum += xsh[(tb + i + 31) * CH + c] - xsh[(tb + i - 1) * CH + c];
            ssh[(tb + i) * 65 + c] = ssum * 0.03125f;
        }
    }
    __syncthreads();

    if (tid < 128) {
        const int t = tid;
        float hid[16];
        #pragma unroll
        for (int j = 0; j < 16; ++j) hid[j] = b1s[j];
        for (int cc = 0; cc < CH; ++cc) {
            float sv = ssh[t * 65 + cc];
            #pragma unroll
            for (int j = 0; j < 16; ++j) hid[j] = fmaf(sv, w1s[cc * 16 + j], hid[j]);
        }
        #pragma unroll
        for (int j = 0; j < 16; ++j) hid[j] = fmaxf(hid[j], 0.f);
        for (int cc = 0; cc < CH; ++cc) {
            float v = b2s[cc];
            #pragma unroll
            for (int j = 0; j < 16; ++j) v = fmaf(hid[j], w2s[j * CH + cc], v);
            g_a[(b * TT + t0 + t) * CH + cc] = 1.f / (1.f + expf(-v));
        }
    }
}

// ---------------------------------------------------------------------------
// Main fused kernel helpers: register-blocked GEMM with packed f32x2 FMA.
// Thread layout: 256 threads = 16(ty: token groups of 4) x 16(tx).
// Each thread owns tokens t = ty*4+i (i<4), columns j = tx*4 + 64*q + e.
// ---------------------------------------------------------------------------
__device__ __forceinline__ unsigned long long pack2(float lo, float hi) {
    unsigned long long r;
    asm("mov.b64 %0, {%1, %2};" : "=l"(r)
        : "r"(__float_as_uint(lo)), "r"(__float_as_uint(hi)));
    return r;
}
__device__ __forceinline__ void fma2(unsigned long long& d,
                                     unsigned long long a, unsigned long long b) {
    asm("fma.rn.f32x2 %0, %1, %2, %0;" : "+l"(d) : "l"(a), "l"(b));
}
__device__ __forceinline__ void unpack2(unsigned long long v, float& lo, float& hi) {
    unsigned int a, b2;
    asm("mov.b64 {%0, %1}, %2;" : "=r"(a), "=r"(b2) : "l"(v));
    lo = __uint_as_float(a); hi = __uint_as_float(b2);
}

// Gated-window GEMM: out[t][j] = relu( sum_{f>=F0,c} xc[t+f-31][c]*a[t][c]*W[(f-F0)*64+c][j] + bias[j] )
template<int NOUT, int F0>
__device__ __forceinline__ void gemm_gated(
    const float* __restrict__ Wg, const float* __restrict__ bias,
    const float* __restrict__ xs, const float* __restrict__ as_,
    float* __restrict__ wst, float* __restrict__ outp, int ostride, int tid)
{
    constexpr int KTOT = (WF - F0) * CH;
    constexpr int NCH  = KTOT / 32;
    constexpr int QN   = NOUT / 64;
    constexpr int LD4  = NOUT / 32;   // float4 per thread per 32-row chunk

    const int ty = tid >> 4, tx = tid & 15;

    unsigned long long acc[4][QN][2];
    #pragma unroll
    for (int i = 0; i < 4; ++i)
        #pragma unroll
        for (int q = 0; q < QN; ++q) { acc[i][q][0] = 0ull; acc[i][q][1] = 0ull; }

    // stage chunk 0
    {
        const float4* src = (const float4*)Wg;
        float4* dst = (float4*)wst;
        #pragma unroll
        for (int r = 0; r < LD4; ++r) dst[tid + 256 * r] = src[tid + 256 * r];
    }
    __syncthreads();

    for (int ch = 0; ch < NCH; ++ch) {
        float4 pre[LD4];
        if (ch + 1 < NCH) {
            const float4* src = (const float4*)(Wg + (ch + 1) * 32 * NOUT);
            #pragma unroll
            for (int r = 0; r < LD4; ++r) pre[r] = src[tid + 256 * r];
        }
        const float* wb = wst + (ch & 1) * (32 * NOUT);
        #pragma unroll
        for (int kk = 0; kk < 32; ++kk) {
            const int kp = ch * 32 + kk;
            const int f  = F0 + (kp >> 6);
            const int c  = kp & 63;
            unsigned long long avp[4];
            #pragma unroll
            for (int i = 0; i < 4; ++i) {
                int t = ty * 4 + i;
                float av = xs[(t + f) * CH + c] * as_[t * CH + c];
                avp[i] = pack2(av, av);
            }
            #pragma unroll
            for (int q = 0; q < QN; ++q) {
                float4 w4 = *(const float4*)(wb + kk * NOUT + tx * 4 + 64 * q);
                unsigned long long w01 = pack2(w4.x, w4.y);
                unsigned long long w23 = pack2(w4.z, w4.w);
                #pragma unroll
                for (int i = 0; i < 4; ++i) {
                    fma2(acc[i][q][0], avp[i], w01);
                    fma2(acc[i][q][1], avp[i], w23);
                }
            }
        }
        __syncthreads();
        if (ch + 1 < NCH) {
            float4* dst = (float4*)(wst + ((ch + 1) & 1) * (32 * NOUT));
            #pragma unroll
            for (int r = 0; r < LD4; ++r) dst[tid + 256 * r] = pre[r];
            __syncthreads();
        }
    }
    // epilogue: bias + relu -> smem
    #pragma unroll
    for (int i = 0; i < 4; ++i) {
        int t = ty * 4 + i;
        #pragma unroll
        for (int q = 0; q < QN; ++q) {
            #pragma unroll
            for (int p = 0; p < 2; ++p) {
                float v0, v1;
                unpack2(acc[i][q][p], v0, v1);
                int j0 = tx * 4 + 64 * q + p * 2;
                v0 = fmaxf(v0 + bias[j0], 0.f);
                v1 = fmaxf(v1 + bias[j0 + 1], 0.f);
                outp[t * ostride + j0]     = v0;
                outp[t * ostride + j0 + 1] = v1;
            }
        }
    }
}

// Plain GEMM from smem A (stride 256), K=256, NOUT=128, relu.
__device__ __forceinline__ void gemm_plain_h2(
    const float* __restrict__ Wg, const float* __restrict__ bias,
    const float* __restrict__ As, float* __restrict__ wst,
    float* __restrict__ outp, int ostride, int tid)
{
    constexpr int NOUT = 128, KTOT = 256, NCH = KTOT / 32, QN = 2, LD4 = 4;
    const int ty = tid >> 4, tx = tid & 15;

    unsigned long long acc[4][QN][2];
    #pragma unroll
    for (int i = 0; i < 4; ++i)
        #pragma unroll
        for (int q = 0; q < QN; ++q) { acc[i][q][0] = 0ull; acc[i][q][1] = 0ull; }

    {
        const float4* src = (const float4*)Wg;
        float4* dst = (float4*)wst;
        #pragma unroll
        for (int r = 0; r < LD4; ++r) dst[tid + 256 * r] = src[tid + 256 * r];
    }
    __syncthreads();

    for (int ch = 0; ch < NCH; ++ch) {
        float4 pre[LD4];
        if (ch + 1 < NCH) {
            const float4* src = (const float4*)(Wg + (ch + 1) * 32 * NOUT);
            #pragma unroll
            for (int r = 0; r < LD4; ++r) pre[r] = src[tid + 256 * r];
        }
        const float* wb = wst + (ch & 1) * (32 * NOUT);
        #pragma unroll
        for (int kk = 0; kk < 32; ++kk) {
            const int kp = ch * 32 + kk;
            unsigned long long avp[4];
            #pragma unroll
            for (int i = 0; i < 4; ++i) {
                int t = ty * 4 + i;
                float av = As[t * 256 + kp];
                avp[i] = pack2(av, av);
            }
            #pragma unroll
            for (int q = 0; q < QN; ++q) {
                float4 w4 = *(const float4*)(wb + kk * NOUT + tx * 4 + 64 * q);
                unsigned long long w01 = pack2(w4.x, w4.y);
                unsigned long long w23 = pack2(w4.z, w4.w);
                #pragma unroll
                for (int i = 0; i < 4; ++i) {
                    fma2(acc[i][q][0], avp[i], w01);
                    fma2(acc[i][q][1], avp[i], w23);
                }
            }
        }
        __syncthreads();
        if (ch + 1 < NCH) {
            float4* dst = (float4*)(wst + ((ch + 1) & 1) * (32 * NOUT));
            #pragma unroll
            for (int r = 0; r < LD4; ++r) dst[tid + 256 * r] = pre[r];
            __syncthreads();
        }
    }
    #pragma unroll
    for (int i = 0; i < 4; ++i) {
        int t = ty * 4 + i;
        #pragma unroll
        for (int q = 0; q < QN; ++q) {
            #pragma unroll
            for (int p = 0; p < 2; ++p) {
                float v0, v1;
                unpack2(acc[i][q][p], v0, v1);
                int j0 = tx * 4 + 64 * q + p * 2;
                v0 = fmaxf(v0 + bias[j0], 0.f);
                v1 = fmaxf(v1 + bias[j0 + 1], 0.f);
                outp[t * ostride + j0]     = v0;
                outp[t * ostride + j0 + 1] = v1;
            }
        }
    }
}

// ---------------------------------------------------------------------------
// Kernel 3: main fused kernel. grid 512 blocks x 64 tokens, 256 threads.
// dynamic smem layout (floats):
//   XS   = 0      : 95*64  = 6080     (xc rows t0-31..t0+63)   \ aliased by H2S later
//   AS   = 6080   : 64*64  = 4096                              /
//   H1S  = 10176  : 64*256 = 16384
//   HSS  = 26560  : 64*132 = 8448
//   WST  = 35008  : 2*32*256 = 16384  (double-buffer weight staging)
//   WOS  = 51392  : 512
//   total 51904 floats = 207616 B
// ---------------------------------------------------------------------------
#define OFF_XS  0
#define OFF_AS  6080
#define OFF_H2S 0
#define OFF_H1S 10176
#define OFF_HSS 26560
#define OFF_WST 35008
#define OFF_WOS 51392
#define SMEM3_FLOATS 51904

__global__ __launch_bounds__(256, 1) void main_kernel(
    const float* __restrict__ w1, const float* __restrict__ b1,
    const float* __restrict__ w2, const float* __restrict__ b2,
    const float* __restrict__ sw, const float* __restrict__ sb,
    const float* __restrict__ wo, const float* __restrict__ bo,
    float* __restrict__ out)
{
    extern __shared__ float sm[];
    const int b  = blockIdx.x >> 6;
    const int t0 = (blockIdx.x & 63) << 6;
    const int tid = threadIdx.x;

    // load xc slab (95 rows) and gate tile (64 rows)
    for (int idx = tid; idx < 95 * CH; idx += 256) {
        int r = idx >> 6, cc = idx & 63;
        int t = t0 - 31 + r;
        sm[OFF_XS + idx] = (t >= 0) ? g_xc[(b * TT + t) * CH + cc] : 0.f;
    }
    for (int idx = tid; idx < 64 * CH; idx += 256) {
        int r = idx >> 6, cc = idx & 63;
        sm[OFF_AS + idx] = g_a[(b * TT + t0 + r) * CH + cc];
    }
    for (int idx = tid; idx < 512; idx += 256) sm[OFF_WOS + idx] = wo[idx];
    __syncthreads();

    // phase 1: h1 = relu(flat_long @ w1 + b1)   (K=2048, N=256)
    gemm_gated<256, 0>(w1, b1, sm + OFF_XS, sm + OFF_AS,
                       sm + OFF_WST, sm + OFF_H1S, 256, tid);

    // phase 1b: h_short = relu(flat_short @ sw + sb)  (K=512, N=128, frames 24..31)
    gemm_gated<128, 24>(sw, sb, sm + OFF_XS, sm + OFF_AS,
                        sm + OFF_WST, sm + OFF_HSS, 132, tid);
    __syncthreads();  // before H2S aliases XS/AS

    // phase 2: h2 = relu(h1 @ w2 + b2)  (K=256, N=128)  — writes over XS/AS region
    gemm_plain_h2(w2, b2, sm + OFF_H1S, sm + OFF_WST, sm + OFF_H2S, 132, tid);
    __syncthreads();

    // phase 3: out = sigmoid([h2, h_short] @ wo + bo)
    if (tid < 128) {
        const int t = tid >> 1;
        const int o = tid & 1;
        float acc = bo[o];
        #pragma unroll 4
        for (int k = 0; k < 128; ++k)
            acc = fmaf(sm[OFF_H2S + t * 132 + k], sm[OFF_WOS + k * 2 + o], acc);
        #pragma unroll 4
        for (int k = 0; k < 128; ++k)
            acc = fmaf(sm[OFF_HSS + t * 132 + k], sm[OFF_WOS + (128 + k) * 2 + o], acc);
        out[(b * TT + t0 + t) * 2 + o] = 1.f / (1.f + expf(-acc));
    }
}

// ---------------------------------------------------------------------------
extern "C" void kernel_launch(void* const* d_in, const int* in_sizes, int n_in,
                              void* d_out, int out_size)
{
    const float* x      = (const float*)d_in[0];
    const float* conv_w = (const float*)d_in[1];
    const float* conv_b = (const float*)d_in[2];
    const float* se_w1  = (const float*)d_in[3];
    const float* se_b1  = (const float*)d_in[4];
    const float* se_w2  = (const float*)d_in[5];
    const float* se_b2  = (const float*)d_in[6];
    const float* w1     = (const float*)d_in[7];
    const float* b1     = (const float*)d_in[8];
    const float* w2     = (const float*)d_in[9];
    const float* b2     = (const float*)d_in[10];
    const float* sw     = (const float*)d_in[11];
    const float* sb     = (const float*)d_in[12];
    const float* wo     = (const float*)d_in[13];
    const float* bo     = (const float*)d_in[14];
    float* out = (float*)d_out;

    const int smem2 = 20624 * 4;
    const int smem3 = SMEM3_FLOATS * 4;
    cudaFuncSetAttribute(se_kernel,  cudaFuncAttributeMaxDynamicSharedMemorySize, smem2);
    cudaFuncSetAttribute(main_kernel, cudaFuncAttributeMaxDynamicSharedMemorySize, smem3);

    conv_kernel<<<BATCH * 64, 256>>>(x, conv_w, conv_b);
    se_kernel<<<BATCH * 32, 256, smem2>>>(se_w1, se_b1, se_w2, se_b2);
    main_kernel<<<BATCH * 64, 256, smem3>>>(w1, b1, w2, b2, sw, sb, wo, bo, out);
}